// round 4
// baseline (speedup 1.0000x reference)
#include <cuda_runtime.h>
#include <cstdint>
#include <math.h>

// Problem dims (fixed)
#define Bb 4
#define Ss 2048
#define Ee 512
#define Hh 1024
#define BS (Bb*Ss)       // 8192 token rows
#define BE (Bb*Ee)       // 2048 external rows
#define LS (Ee+1)        // 513 score columns

// Scratch (device globals; allocation-free)
__device__ float g_q [BS*Hh];
__device__ float g_kt[BS*Hh];
__device__ float g_vt[BS*Hh];
__device__ float g_ke[BE*Hh];
__device__ float g_ve[BE*Hh];
__device__ float g_sc[(size_t)BS*LS];

#define HIMASK 0xFFFFE000u
#define RS 264                   // smem row stride (floats), 264 % 32 == 8
#define TILE_FLOATS (16 * RS)
#define SMEM_BYTES (4 * TILE_FLOATS * 4)   // As x2 + Bs x2 = 67584 B

typedef unsigned long long ull;

// Split fp32 into (hi,lo) tf32 pair packed in 64 bits: lo word = hi part.
__device__ __forceinline__ ull split_pack(float x)
{
    uint32_t h = __float_as_uint(x) & HIMASK;
    uint32_t l = __float_as_uint(x - __uint_as_float(h)) & HIMASK;
    return (ull)h | ((ull)l << 32);
}
// Split two fp32 into interleaved uint4 {hx,lx,hy,ly}.
__device__ __forceinline__ uint4 split4(float x, float y)
{
    uint32_t hx = __float_as_uint(x) & HIMASK;
    uint32_t lx = __float_as_uint(x - __uint_as_float(hx)) & HIMASK;
    uint32_t hy = __float_as_uint(y) & HIMASK;
    uint32_t ly = __float_as_uint(y - __uint_as_float(hy)) & HIMASK;
    return make_uint4(hx, lx, hy, ly);
}

__device__ __forceinline__ void mma8(float* d, const uint32_t* a, const uint32_t* b)
{
    asm volatile(
        "mma.sync.aligned.m16n8k8.row.col.f32.tf32.tf32.f32 "
        "{%0,%1,%2,%3}, {%4,%5,%6,%7}, {%8,%9}, {%0,%1,%2,%3};"
        : "+f"(d[0]), "+f"(d[1]), "+f"(d[2]), "+f"(d[3])
        : "r"(a[0]), "r"(a[1]), "r"(a[2]), "r"(a[3]),
          "r"(b[0]), "r"(b[1]));
}

// One BK=16 stage from pre-split smem tiles ([k][2*mn], stride RS).
// Needs in scope: wm, wn, gid, tg, float acc[4][4][4].
#define FRAG_COMPUTE(Abuf, Bbuf)                                              \
  do {                                                                        \
    _Pragma("unroll")                                                         \
    for (int kk = 0; kk < 16; kk += 8) {                                      \
      uint32_t ah[4][4], al[4][4], bh[4][2], bl[4][2];                        \
      _Pragma("unroll")                                                       \
      for (int mt = 0; mt < 4; mt++) {                                        \
        int mbase = wm * 64 + mt * 16 + gid;                                  \
        _Pragma("unroll")                                                     \
        for (int h = 0; h < 2; h++) {                                         \
          uint2 v0 = *(const uint2*)&(Abuf)[(kk + tg + h*4) * RS + 2*mbase];  \
          uint2 v1 = *(const uint2*)&(Abuf)[(kk + tg + h*4) * RS + 2*(mbase+8)];\
          ah[mt][h*2+0] = v0.x; al[mt][h*2+0] = v0.y;                         \
          ah[mt][h*2+1] = v1.x; al[mt][h*2+1] = v1.y;                         \
        }                                                                     \
      }                                                                       \
      _Pragma("unroll")                                                       \
      for (int nt = 0; nt < 4; nt++) {                                        \
        int nbase = wn * 32 + nt * 8 + gid;                                   \
        uint2 w0 = *(const uint2*)&(Bbuf)[(kk + tg) * RS + 2*nbase];          \
        uint2 w1 = *(const uint2*)&(Bbuf)[(kk + tg + 4) * RS + 2*nbase];      \
        bh[nt][0] = w0.x; bl[nt][0] = w0.y;                                   \
        bh[nt][1] = w1.x; bl[nt][1] = w1.y;                                   \
      }                                                                       \
      _Pragma("unroll")                                                       \
      for (int mt = 0; mt < 4; mt++)                                          \
        _Pragma("unroll")                                                     \
        for (int nt = 0; nt < 4; nt++) {                                      \
          mma8(acc[mt][nt], ah[mt], bh[nt]);                                  \
          mma8(acc[mt][nt], ah[mt], bl[nt]);                                  \
          mma8(acc[mt][nt], al[mt], bh[nt]);                                  \
        }                                                                     \
    }                                                                         \
  } while (0)

#define ACC_INIT                                                              \
    float acc[4][4][4];                                                      \
    _Pragma("unroll")                                                         \
    for (int i = 0; i < 4; i++)                                               \
      _Pragma("unroll")                                                       \
      for (int j = 0; j < 4; j++)                                             \
        _Pragma("unroll")                                                     \
        for (int t = 0; t < 4; t++) acc[i][j][t] = 0.f;

#define WARP_IDS                                                              \
    const int tid = threadIdx.x;                                              \
    const int warp = tid >> 5, lane = tid & 31;                               \
    const int wm = warp & 1, wn = warp >> 1;                                  \
    const int gid = lane >> 2, tg = lane & 3;

#define SMEM_PTRS                                                             \
    extern __shared__ float smem[];                                           \
    float* const AsBase = smem;                                               \
    float* const BsBase = smem + 2 * TILE_FLOATS;

// Transposed split store of one fp32 A value: As[k][2m] = (hi,lo).
#define STS_A_SPLIT(Abuf, k, m, val) \
    *(ull*)&(Abuf)[(k) * RS + 2 * (m)] = split_pack(val)

// ---------------------------------------------------------------------------
// GEMM NN + bias: C[M,N] = A[M,K] @ W[K,N] + bias[N].  128x128 tile, BK=16.
// ---------------------------------------------------------------------------
__global__ void __launch_bounds__(256, 2) gemm_nn_bias(
    const float* __restrict__ A, const float* __restrict__ W,
    const float* __restrict__ bias, float* __restrict__ C,
    int M, int N, int K)
{
    SMEM_PTRS;
    const int bm = blockIdx.y * 128;
    const int bn = blockIdx.x * 128;
    WARP_IDS;
    const int ar = tid >> 2, ac = (tid & 3) << 2;
    const int br = tid >> 5, bc = (tid & 31) << 2;

    ACC_INIT;
    float4 pa0, pa1, pb0, pb1;

#define LOAD_P(k0)                                                            \
    do {                                                                      \
        pa0 = *(const float4*)(A + (size_t)(bm + ar) * K + (k0) + ac);        \
        pa1 = *(const float4*)(A + (size_t)(bm + ar + 64) * K + (k0) + ac);   \
        pb0 = *(const float4*)(W + (size_t)((k0) + br) * N + bn + bc);        \
        pb1 = *(const float4*)(W + (size_t)((k0) + br + 8) * N + bn + bc);    \
    } while (0)
#define STS_P(As_, Bs_)                                                       \
    do {                                                                      \
        STS_A_SPLIT(As_, ac + 0, ar, pa0.x);                                  \
        STS_A_SPLIT(As_, ac + 1, ar, pa0.y);                                  \
        STS_A_SPLIT(As_, ac + 2, ar, pa0.z);                                  \
        STS_A_SPLIT(As_, ac + 3, ar, pa0.w);                                  \
        STS_A_SPLIT(As_, ac + 0, ar + 64, pa1.x);                             \
        STS_A_SPLIT(As_, ac + 1, ar + 64, pa1.y);                             \
        STS_A_SPLIT(As_, ac + 2, ar + 64, pa1.z);                             \
        STS_A_SPLIT(As_, ac + 3, ar + 64, pa1.w);                             \
        *(uint4*)&(Bs_)[br * RS + 2*bc]           = split4(pb0.x, pb0.y);     \
        *(uint4*)&(Bs_)[br * RS + 2*bc + 4]       = split4(pb0.z, pb0.w);     \
        *(uint4*)&(Bs_)[(br + 8) * RS + 2*bc]     = split4(pb1.x, pb1.y);     \
        *(uint4*)&(Bs_)[(br + 8) * RS + 2*bc + 4] = split4(pb1.z, pb1.w);     \
    } while (0)

    LOAD_P(0);
    STS_P(AsBase, BsBase);
    __syncthreads();
    int buf = 0;
    for (int k0 = 0; k0 < K; k0 += 16) {
        const bool nxt = (k0 + 16 < K);
        if (nxt) LOAD_P(k0 + 16);
        FRAG_COMPUTE((AsBase + buf * TILE_FLOATS), (BsBase + buf * TILE_FLOATS));
        if (nxt) STS_P((AsBase + (buf ^ 1) * TILE_FLOATS),
                       (BsBase + (buf ^ 1) * TILE_FLOATS));
        __syncthreads();
        buf ^= 1;
    }
#undef LOAD_P
#undef STS_P

    #pragma unroll
    for (int mt = 0; mt < 4; mt++) {
        int r0 = bm + wm * 64 + mt * 16 + gid;
        #pragma unroll
        for (int nt = 0; nt < 4; nt++) {
            int col = bn + wn * 32 + nt * 8 + 2 * tg;
            float2 bi = *(const float2*)(bias + col);
            float2 o0 = make_float2(acc[mt][nt][0] + bi.x,
                                    acc[mt][nt][1] + bi.y);
            float2 o1 = make_float2(acc[mt][nt][2] + bi.x,
                                    acc[mt][nt][3] + bi.y);
            *(float2*)(C + (size_t)r0 * N + col) = o0;
            *(float2*)(C + (size_t)(r0 + 8) * N + col) = o1;
        }
    }
}

// ---------------------------------------------------------------------------
// Batched NT GEMM: SC[b, s, 1+e] = Q[b,s,:] . KE[b,e,:]  (K = Hh)
// ---------------------------------------------------------------------------
__global__ void __launch_bounds__(256, 2) gemm_scores_nt(
    const float* __restrict__ Q, const float* __restrict__ KE,
    float* __restrict__ SC)
{
    SMEM_PTRS;
    const int b = blockIdx.z;
    const float* Aq = Q  + (size_t)b * Ss * Hh;
    const float* Bk = KE + (size_t)b * Ee * Hh;

    const int bm = blockIdx.y * 128;
    const int bn = blockIdx.x * 128;
    WARP_IDS;
    const int ar = tid >> 2, ac = (tid & 3) << 2;

    ACC_INIT;
    float4 pa0, pa1, pb0, pb1;

#define LOAD_S(k0)                                                            \
    do {                                                                      \
        pa0 = *(const float4*)(Aq + (size_t)(bm + ar) * Hh + (k0) + ac);      \
        pa1 = *(const float4*)(Aq + (size_t)(bm + ar + 64) * Hh + (k0) + ac); \
        pb0 = *(const float4*)(Bk + (size_t)(bn + ar) * Hh + (k0) + ac);      \
        pb1 = *(const float4*)(Bk + (size_t)(bn + ar + 64) * Hh + (k0) + ac); \
    } while (0)
#define STS_S(As_, Bs_)                                                       \
    do {                                                                      \
        STS_A_SPLIT(As_, ac + 0, ar, pa0.x);                                  \
        STS_A_SPLIT(As_, ac + 1, ar, pa0.y);                                  \
        STS_A_SPLIT(As_, ac + 2, ar, pa0.z);                                  \
        STS_A_SPLIT(As_, ac + 3, ar, pa0.w);                                  \
        STS_A_SPLIT(As_, ac + 0, ar + 64, pa1.x);                             \
        STS_A_SPLIT(As_, ac + 1, ar + 64, pa1.y);                             \
        STS_A_SPLIT(As_, ac + 2, ar + 64, pa1.z);                             \
        STS_A_SPLIT(As_, ac + 3, ar + 64, pa1.w);                             \
        STS_A_SPLIT(Bs_, ac + 0, ar, pb0.x);                                  \
        STS_A_SPLIT(Bs_, ac + 1, ar, pb0.y);                                  \
        STS_A_SPLIT(Bs_, ac + 2, ar, pb0.z);                                  \
        STS_A_SPLIT(Bs_, ac + 3, ar, pb0.w);                                  \
        STS_A_SPLIT(Bs_, ac + 0, ar + 64, pb1.x);                             \
        STS_A_SPLIT(Bs_, ac + 1, ar + 64, pb1.y);                             \
        STS_A_SPLIT(Bs_, ac + 2, ar + 64, pb1.z);                             \
        STS_A_SPLIT(Bs_, ac + 3, ar + 64, pb1.w);                             \
    } while (0)

    LOAD_S(0);
    STS_S(AsBase, BsBase);
    __syncthreads();
    int buf = 0;
    for (int k0 = 0; k0 < Hh; k0 += 16) {
        const bool nxt = (k0 + 16 < Hh);
        if (nxt) LOAD_S(k0 + 16);
        FRAG_COMPUTE((AsBase + buf * TILE_FLOATS), (BsBase + buf * TILE_FLOATS));
        if (nxt) STS_S((AsBase + (buf ^ 1) * TILE_FLOATS),
                       (BsBase + (buf ^ 1) * TILE_FLOATS));
        __syncthreads();
        buf ^= 1;
    }
#undef LOAD_S
#undef STS_S

    #pragma unroll
    for (int mt = 0; mt < 4; mt++) {
        int row = b * Ss + bm + wm * 64 + mt * 16 + gid;
        #pragma unroll
        for (int nt = 0; nt < 4; nt++) {
            int col = bn + wn * 32 + nt * 8 + 2 * tg;
            size_t base0 = (size_t)row * LS + 1 + col;
            size_t base1 = (size_t)(row + 8) * LS + 1 + col;
            SC[base0]     = acc[mt][nt][0];
            SC[base0 + 1] = acc[mt][nt][1];
            SC[base1]     = acc[mt][nt][2];
            SC[base1 + 1] = acc[mt][nt][3];
        }
    }
}

// ---------------------------------------------------------------------------
// Self-dot: SC[row, 0] = q[row,:] . k_tok[row,:]   (fp32, one warp per row)
// ---------------------------------------------------------------------------
__global__ void self_dot_kernel(const float* __restrict__ q,
                                const float* __restrict__ kt,
                                float* __restrict__ SC)
{
    int row  = blockIdx.x * 8 + (threadIdx.x >> 5);
    int lane = threadIdx.x & 31;
    const float4* q4 = (const float4*)(q  + (size_t)row * Hh);
    const float4* k4 = (const float4*)(kt + (size_t)row * Hh);
    float sum = 0.f;
    #pragma unroll
    for (int i = lane; i < Hh / 4; i += 32) {
        float4 a = q4[i], b = k4[i];
        sum += a.x * b.x + a.y * b.y + a.z * b.z + a.w * b.w;
    }
    #pragma unroll
    for (int o = 16; o; o >>= 1) sum += __shfl_xor_sync(0xffffffffu, sum, o);
    if (lane == 0) SC[(size_t)row * LS] = sum;
}

// ---------------------------------------------------------------------------
// Softmax over rows of length LS=513, in place. One block (128 thr) per row.
// ---------------------------------------------------------------------------
__global__ void softmax_kernel(float* __restrict__ SC)
{
    float* s = SC + (size_t)blockIdx.x * LS;
    const int tid = threadIdx.x;
    __shared__ float redm[4];
    __shared__ float reds[4];

    float v[5];
    float lmax = -INFINITY;
    #pragma unroll
    for (int i = 0; i < 5; i++) {
        int idx = tid + 128 * i;
        v[i] = (idx < LS) ? s[idx] : -INFINITY;
        lmax = fmaxf(lmax, v[i]);
    }
    #pragma unroll
    for (int o = 16; o; o >>= 1)
        lmax = fmaxf(lmax, __shfl_xor_sync(0xffffffffu, lmax, o));
    if ((tid & 31) == 0) redm[tid >> 5] = lmax;
    __syncthreads();
    float m = fmaxf(fmaxf(redm[0], redm[1]), fmaxf(redm[2], redm[3]));

    float lsum = 0.f;
    #pragma unroll
    for (int i = 0; i < 5; i++) {
        v[i] = expf(v[i] - m);
        lsum += v[i];
    }
    #pragma unroll
    for (int o = 16; o; o >>= 1) lsum += __shfl_xor_sync(0xffffffffu, lsum, o);
    if ((tid & 31) == 0) reds[tid >> 5] = lsum;
    __syncthreads();
    float inv = 1.f / (reds[0] + reds[1] + reds[2] + reds[3]);

    #pragma unroll
    for (int i = 0; i < 5; i++) {
        int idx = tid + 128 * i;
        if (idx < LS) s[idx] = v[i] * inv;
    }
}

// ---------------------------------------------------------------------------
// Context: O[b,s,:] = p0 * v_tok[b,s,:] + P[b,s,1:] @ V_ext[b]  (K = Ee)
// ---------------------------------------------------------------------------
__global__ void __launch_bounds__(256, 2) gemm_ctx(
    const float* __restrict__ P, const float* __restrict__ VE,
    const float* __restrict__ VT, float* __restrict__ O)
{
    SMEM_PTRS;
    const int b = blockIdx.z;
    const float* Bbase = VE + (size_t)b * Ee * Hh;

    const int bm = blockIdx.y * 128;
    const int bn = blockIdx.x * 128;
    WARP_IDS;
    const int ar = tid >> 2, ac = (tid & 3) << 2;
    const int br = tid >> 5, bc = (tid & 31) << 2;

    ACC_INIT;
    float pav[2][4];
    float4 pb0, pb1;

#define LOAD_C(k0)                                                            \
    do {                                                                      \
        const float* ap0 = P + (size_t)(b * Ss + bm + ar) * LS + 1 + (k0) + ac;      \
        const float* ap1 = P + (size_t)(b * Ss + bm + ar + 64) * LS + 1 + (k0) + ac; \
        pav[0][0] = ap0[0]; pav[0][1] = ap0[1];                               \
        pav[0][2] = ap0[2]; pav[0][3] = ap0[3];                               \
        pav[1][0] = ap1[0]; pav[1][1] = ap1[1];                               \
        pav[1][2] = ap1[2]; pav[1][3] = ap1[3];                               \
        pb0 = *(const float4*)(Bbase + (size_t)((k0) + br) * Hh + bn + bc);   \
        pb1 = *(const float4*)(Bbase + (size_t)((k0) + br + 8) * Hh + bn + bc); \
    } while (0)
#define STS_C(As_, Bs_)                                                       \
    do {                                                                      \
        STS_A_SPLIT(As_, ac + 0, ar, pav[0][0]);                              \
        STS_A_SPLIT(As_, ac + 1, ar, pav[0][1]);                              \
        STS_A_SPLIT(As_, ac + 2, ar, pav[0][2]);                              \
        STS_A_SPLIT(As_, ac + 3, ar, pav[0][3]);                              \
        STS_A_SPLIT(As_, ac + 0, ar + 64, pav[1][0]);                         \
        STS_A_SPLIT(As_, ac + 1, ar + 64, pav[1][1]);                         \
        STS_A_SPLIT(As_, ac + 2, ar + 64, pav[1][2]);                         \
        STS_A_SPLIT(As_, ac + 3, ar + 64, pav[1][3]);                         \
        *(uint4*)&(Bs_)[br * RS + 2*bc]           = split4(pb0.x, pb0.y);     \
        *(uint4*)&(Bs_)[br * RS + 2*bc + 4]       = split4(pb0.z, pb0.w);     \
        *(uint4*)&(Bs_)[(br + 8) * RS + 2*bc]     = split4(pb1.x, pb1.y);     \
        *(uint4*)&(Bs_)[(br + 8) * RS + 2*bc + 4] = split4(pb1.z, pb1.w);     \
    } while (0)

    LOAD_C(0);
    STS_C(AsBase, BsBase);
    __syncthreads();
    int buf = 0;
    for (int k0 = 0; k0 < Ee; k0 += 16) {
        const bool nxt = (k0 + 16 < Ee);
        if (nxt) LOAD_C(k0 + 16);
        FRAG_COMPUTE((AsBase + buf * TILE_FLOATS), (BsBase + buf * TILE_FLOATS));
        if (nxt) STS_C((AsBase + (buf ^ 1) * TILE_FLOATS),
                       (BsBase + (buf ^ 1) * TILE_FLOATS));
        __syncthreads();
        buf ^= 1;
    }
#undef LOAD_C
#undef STS_C

    #pragma unroll
    for (int mt = 0; mt < 4; mt++) {
        int r0 = b * Ss + bm + wm * 64 + mt * 16 + gid;
        int r1 = r0 + 8;
        float p0 = P[(size_t)r0 * LS];
        float p1 = P[(size_t)r1 * LS];
        #pragma unroll
        for (int nt = 0; nt < 4; nt++) {
            int col = bn + wn * 32 + nt * 8 + 2 * tg;
            float2 v0 = *(const float2*)(VT + (size_t)r0 * Hh + col);
            float2 v1 = *(const float2*)(VT + (size_t)r1 * Hh + col);
            float2 o0 = make_float2(fmaf(p0, v0.x, acc[mt][nt][0]),
                                    fmaf(p0, v0.y, acc[mt][nt][1]));
            float2 o1 = make_float2(fmaf(p1, v1.x, acc[mt][nt][2]),
                                    fmaf(p1, v1.y, acc[mt][nt][3]));
            *(float2*)(O + (size_t)r0 * Hh + col) = o0;
            *(float2*)(O + (size_t)r1 * Hh + col) = o1;
        }
    }
}

// ---------------------------------------------------------------------------
extern "C" void kernel_launch(void* const* d_in, const int* in_sizes, int n_in,
                              void* d_out, int out_size)
{
    const float* hs  = (const float*)d_in[0];
    const float* ext = (const float*)d_in[1];
    const float* Wq  = (const float*)d_in[2];
    const float* bq  = (const float*)d_in[3];
    const float* Wk  = (const float*)d_in[4];
    const float* bk  = (const float*)d_in[5];
    const float* Wv  = (const float*)d_in[6];
    const float* bv  = (const float*)d_in[7];
    float* out = (float*)d_out;

    float *q, *kt, *vt, *ke, *ve, *sc;
    cudaGetSymbolAddress((void**)&q,  g_q);
    cudaGetSymbolAddress((void**)&kt, g_kt);
    cudaGetSymbolAddress((void**)&vt, g_vt);
    cudaGetSymbolAddress((void**)&ke, g_ke);
    cudaGetSymbolAddress((void**)&ve, g_ve);
    cudaGetSymbolAddress((void**)&sc, g_sc);

    cudaFuncSetAttribute(gemm_nn_bias,
        cudaFuncAttributeMaxDynamicSharedMemorySize, SMEM_BYTES);
    cudaFuncSetAttribute(gemm_scores_nt,
        cudaFuncAttributeMaxDynamicSharedMemorySize, SMEM_BYTES);
    cudaFuncSetAttribute(gemm_ctx,
        cudaFuncAttributeMaxDynamicSharedMemorySize, SMEM_BYTES);

    dim3 blk(256);

    // Projections (tensor-core 3xTF32, pre-split smem)
    gemm_nn_bias<<<dim3(Hh / 128, BS / 128), blk, SMEM_BYTES>>>(hs,  Wq, bq, q,  BS, Hh, Hh);
    gemm_nn_bias<<<dim3(Hh / 128, BS / 128), blk, SMEM_BYTES>>>(hs,  Wk, bk, kt, BS, Hh, Hh);
    gemm_nn_bias<<<dim3(Hh / 128, BS / 128), blk, SMEM_BYTES>>>(hs,  Wv, bv, vt, BS, Hh, Hh);
    gemm_nn_bias<<<dim3(Hh / 128, BE / 128), blk, SMEM_BYTES>>>(ext, Wk, bk, ke, BE, Hh, Hh);
    gemm_nn_bias<<<dim3(Hh / 128, BE / 128), blk, SMEM_BYTES>>>(ext, Wv, bv, ve, BE, Hh, Hh);

    // Scores
    self_dot_kernel<<<BS / 8, 256>>>(q, kt, sc);
    gemm_scores_nt<<<dim3(Ee / 128, Ss / 128, Bb), blk, SMEM_BYTES>>>(q, ke, sc);

    // Softmax
    softmax_kernel<<<BS, 128>>>(sc);

    // Context
    gemm_ctx<<<dim3(Hh / 128, Ss / 128, Bb), blk, SMEM_BYTES>>>(sc, ve, vt, out);
}

// round 5
// speedup vs baseline: 1.4506x; 1.4506x over previous
#include <cuda_runtime.h>
#include <cstdint>
#include <math.h>

// Problem dims (fixed)
#define Bb 4
#define Ss 2048
#define Ee 512
#define Hh 1024
#define BS (Bb*Ss)       // 8192 token rows
#define BE (Bb*Ee)       // 2048 external rows
#define LS (Ee+1)        // 513 score columns

// Scratch (device globals; allocation-free)
__device__ float g_q [BS*Hh];
__device__ float g_kt[BS*Hh];
__device__ float g_vt[BS*Hh];
__device__ float g_ke[BE*Hh];
__device__ float g_ve[BE*Hh];
__device__ float g_sc[(size_t)BS*LS];

#define HIMASK 0xFFFFE000u
#define RSA 264                  // A smem row stride (floats): 256 + 8 pad
#define RSB 136                  // B smem row stride (floats): 128 + 8 pad
#define AT_FLOATS (16 * RSA)
#define BT_FLOATS (16 * RSB)
#define SMEM_BYTES ((2 * AT_FLOATS + 2 * BT_FLOATS) * 4)   // 51200 B

// Split fp32 x into tf32 hi/lo
__device__ __forceinline__ void split_tf32(float x, uint32_t &h, uint32_t &l)
{
    uint32_t hb = __float_as_uint(x) & HIMASK;
    h = hb;
    float r = x - __uint_as_float(hb);
    l = __float_as_uint(r) & HIMASK;
}

__device__ __forceinline__ void mma8(float* d, const uint32_t* a, const uint32_t* b)
{
    asm volatile(
        "mma.sync.aligned.m16n8k8.row.col.f32.tf32.tf32.f32 "
        "{%0,%1,%2,%3}, {%4,%5,%6,%7}, {%8,%9}, {%0,%1,%2,%3};"
        : "+f"(d[0]), "+f"(d[1]), "+f"(d[2]), "+f"(d[3])
        : "r"(a[0]), "r"(a[1]), "r"(a[2]), "r"(a[3]),
          "r"(b[0]), "r"(b[1]));
}

// One BK=16 stage. A tile [k][m] stride RSA, B tile [k][n] stride RSB.
// Needs: wm (0..3), wn (0..3), gid, tg, float acc[4][4][4].
#define FRAG_COMPUTE(Abuf, Bbuf)                                              \
  do {                                                                        \
    _Pragma("unroll")                                                         \
    for (int kk = 0; kk < 16; kk += 8) {                                      \
      uint32_t ah[4][4], al[4][4], bh[4][2], bl[4][2];                        \
      _Pragma("unroll")                                                       \
      for (int mt = 0; mt < 4; mt++) {                                        \
        int mbase = wm * 64 + mt * 16 + gid;                                  \
        _Pragma("unroll")                                                     \
        for (int h = 0; h < 2; h++) {                                         \
          float v0 = (Abuf)[(kk + tg + h * 4) * RSA + mbase];                 \
          float v1 = (Abuf)[(kk + tg + h * 4) * RSA + mbase + 8];             \
          split_tf32(v0, ah[mt][h * 2 + 0], al[mt][h * 2 + 0]);               \
          split_tf32(v1, ah[mt][h * 2 + 1], al[mt][h * 2 + 1]);               \
        }                                                                     \
      }                                                                       \
      _Pragma("unroll")                                                       \
      for (int nt = 0; nt < 4; nt++) {                                        \
        int nbase = wn * 32 + nt * 8 + gid;                                   \
        float w0 = (Bbuf)[(kk + tg) * RSB + nbase];                           \
        float w1 = (Bbuf)[(kk + tg + 4) * RSB + nbase];                       \
        split_tf32(w0, bh[nt][0], bl[nt][0]);                                 \
        split_tf32(w1, bh[nt][1], bl[nt][1]);                                 \
      }                                                                       \
      _Pragma("unroll")                                                       \
      for (int mt = 0; mt < 4; mt++)                                          \
        _Pragma("unroll")                                                     \
        for (int nt = 0; nt < 4; nt++) {                                      \
          mma8(acc[mt][nt], ah[mt], bh[nt]);                                  \
          mma8(acc[mt][nt], ah[mt], bl[nt]);                                  \
          mma8(acc[mt][nt], al[mt], bh[nt]);                                  \
        }                                                                     \
    }                                                                         \
  } while (0)

#define ACC_INIT                                                              \
    float acc[4][4][4];                                                      \
    _Pragma("unroll")                                                         \
    for (int i = 0; i < 4; i++)                                               \
      _Pragma("unroll")                                                       \
      for (int j = 0; j < 4; j++)                                             \
        _Pragma("unroll")                                                     \
        for (int t = 0; t < 4; t++) acc[i][j][t] = 0.f;

// 512 threads = 16 warps: wm in 0..3 (M), wn in 0..3 (N)
#define WARP_IDS                                                              \
    const int tid = threadIdx.x;                                              \
    const int warp = tid >> 5, lane = tid & 31;                               \
    const int wm = warp & 3, wn = warp >> 2;                                  \
    const int gid = lane >> 2, tg = lane & 3;

#define SMEM_PTRS                                                             \
    extern __shared__ float smem[];                                           \
    float* const AsBase = smem;                                               \
    float* const BsBase = smem + 2 * AT_FLOATS;

// ---------------------------------------------------------------------------
// Projections: C[z][M,N] = A[M,K] @ W[z][K,N] + b[z][N].
// Tile 256x128, BK=16, 512 threads. z = blockIdx.z selects weight/out triple.
// ---------------------------------------------------------------------------
__global__ void __launch_bounds__(512, 1) gemm_proj(
    const float* __restrict__ A,
    const float* __restrict__ W0, const float* __restrict__ W1,
    const float* __restrict__ W2,
    const float* __restrict__ b0, const float* __restrict__ b1,
    const float* __restrict__ b2,
    float* __restrict__ C0, float* __restrict__ C1, float* __restrict__ C2)
{
    SMEM_PTRS;
    const int z = blockIdx.z;
    const float* W    = (z == 0) ? W0 : (z == 1) ? W1 : W2;
    const float* bias = (z == 0) ? b0 : (z == 1) ? b1 : b2;
    float* C          = (z == 0) ? C0 : (z == 1) ? C1 : C2;

    const int bm = blockIdx.y * 256;
    const int bn = blockIdx.x * 128;
    WARP_IDS;
    const int ar = tid >> 2, ac = (tid & 3) << 2;   // ar 0..127
    const int br = tid >> 5, bc = (tid & 31) << 2;  // br 0..15

    ACC_INIT;
    float4 pa0, pa1, pb0;

#define LOAD_P(k0)                                                            \
    do {                                                                      \
        pa0 = *(const float4*)(A + (size_t)(bm + ar) * Hh + (k0) + ac);       \
        pa1 = *(const float4*)(A + (size_t)(bm + ar + 128) * Hh + (k0) + ac); \
        pb0 = *(const float4*)(W + (size_t)((k0) + br) * Hh + bn + bc);       \
    } while (0)
#define STS_P(As_, Bs_)                                                       \
    do {                                                                      \
        (As_)[(ac + 0) * RSA + ar] = pa0.x;                                   \
        (As_)[(ac + 1) * RSA + ar] = pa0.y;                                   \
        (As_)[(ac + 2) * RSA + ar] = pa0.z;                                   \
        (As_)[(ac + 3) * RSA + ar] = pa0.w;                                   \
        (As_)[(ac + 0) * RSA + ar + 128] = pa1.x;                             \
        (As_)[(ac + 1) * RSA + ar + 128] = pa1.y;                             \
        (As_)[(ac + 2) * RSA + ar + 128] = pa1.z;                             \
        (As_)[(ac + 3) * RSA + ar + 128] = pa1.w;                             \
        *(float4*)&(Bs_)[br * RSB + bc] = pb0;                                \
    } while (0)

    LOAD_P(0);
    STS_P(AsBase, BsBase);
    __syncthreads();
    int buf = 0;
    for (int k0 = 0; k0 < Hh; k0 += 16) {
        const bool nxt = (k0 + 16 < Hh);
        if (nxt) LOAD_P(k0 + 16);
        FRAG_COMPUTE((AsBase + buf * AT_FLOATS), (BsBase + buf * BT_FLOATS));
        if (nxt) STS_P((AsBase + (buf ^ 1) * AT_FLOATS),
                       (BsBase + (buf ^ 1) * BT_FLOATS));
        __syncthreads();
        buf ^= 1;
    }
#undef LOAD_P
#undef STS_P

    #pragma unroll
    for (int mt = 0; mt < 4; mt++) {
        int r0 = bm + wm * 64 + mt * 16 + gid;
        #pragma unroll
        for (int nt = 0; nt < 4; nt++) {
            int col = bn + wn * 32 + nt * 8 + 2 * tg;
            float2 bi = *(const float2*)(bias + col);
            float2 o0 = make_float2(acc[mt][nt][0] + bi.x,
                                    acc[mt][nt][1] + bi.y);
            float2 o1 = make_float2(acc[mt][nt][2] + bi.x,
                                    acc[mt][nt][3] + bi.y);
            *(float2*)(C + (size_t)r0 * Hh + col) = o0;
            *(float2*)(C + (size_t)(r0 + 8) * Hh + col) = o1;
        }
    }
}

// ---------------------------------------------------------------------------
// Batched NT GEMM: SC[b, s, 1+e] = Q[b,s,:] . KE[b,e,:]  (K = Hh)
// Tile 256(M) x 128(N), 512 threads.
// ---------------------------------------------------------------------------
__global__ void __launch_bounds__(512, 1) gemm_scores_nt(
    const float* __restrict__ Q, const float* __restrict__ KE,
    float* __restrict__ SC)
{
    SMEM_PTRS;
    const int b = blockIdx.z;
    const float* Aq = Q  + (size_t)b * Ss * Hh;
    const float* Bk = KE + (size_t)b * Ee * Hh;

    const int bm = blockIdx.y * 256;
    const int bn = blockIdx.x * 128;
    WARP_IDS;
    const int ar = tid >> 2, ac = (tid & 3) << 2;   // ar 0..127

    ACC_INIT;
    float4 pa0, pa1, pb0;

#define LOAD_S(k0)                                                            \
    do {                                                                      \
        pa0 = *(const float4*)(Aq + (size_t)(bm + ar) * Hh + (k0) + ac);      \
        pa1 = *(const float4*)(Aq + (size_t)(bm + ar + 128) * Hh + (k0) + ac);\
        pb0 = *(const float4*)(Bk + (size_t)(bn + ar) * Hh + (k0) + ac);      \
    } while (0)
#define STS_S(As_, Bs_)                                                       \
    do {                                                                      \
        (As_)[(ac + 0) * RSA + ar] = pa0.x;                                   \
        (As_)[(ac + 1) * RSA + ar] = pa0.y;                                   \
        (As_)[(ac + 2) * RSA + ar] = pa0.z;                                   \
        (As_)[(ac + 3) * RSA + ar] = pa0.w;                                   \
        (As_)[(ac + 0) * RSA + ar + 128] = pa1.x;                             \
        (As_)[(ac + 1) * RSA + ar + 128] = pa1.y;                             \
        (As_)[(ac + 2) * RSA + ar + 128] = pa1.z;                             \
        (As_)[(ac + 3) * RSA + ar + 128] = pa1.w;                             \
        (Bs_)[(ac + 0) * RSB + ar] = pb0.x;                                   \
        (Bs_)[(ac + 1) * RSB + ar] = pb0.y;                                   \
        (Bs_)[(ac + 2) * RSB + ar] = pb0.z;                                   \
        (Bs_)[(ac + 3) * RSB + ar] = pb0.w;                                   \
    } while (0)

    LOAD_S(0);
    STS_S(AsBase, BsBase);
    __syncthreads();
    int buf = 0;
    for (int k0 = 0; k0 < Hh; k0 += 16) {
        const bool nxt = (k0 + 16 < Hh);
        if (nxt) LOAD_S(k0 + 16);
        FRAG_COMPUTE((AsBase + buf * AT_FLOATS), (BsBase + buf * BT_FLOATS));
        if (nxt) STS_S((AsBase + (buf ^ 1) * AT_FLOATS),
                       (BsBase + (buf ^ 1) * BT_FLOATS));
        __syncthreads();
        buf ^= 1;
    }
#undef LOAD_S
#undef STS_S

    #pragma unroll
    for (int mt = 0; mt < 4; mt++) {
        int row = b * Ss + bm + wm * 64 + mt * 16 + gid;
        #pragma unroll
        for (int nt = 0; nt < 4; nt++) {
            int col = bn + wn * 32 + nt * 8 + 2 * tg;
            size_t base0 = (size_t)row * LS + 1 + col;
            size_t base1 = (size_t)(row + 8) * LS + 1 + col;
            SC[base0]     = acc[mt][nt][0];
            SC[base0 + 1] = acc[mt][nt][1];
            SC[base1]     = acc[mt][nt][2];
            SC[base1 + 1] = acc[mt][nt][3];
        }
    }
}

// ---------------------------------------------------------------------------
// Self-dot: SC[row, 0] = q[row,:] . k_tok[row,:]   (fp32, one warp per row)
// ---------------------------------------------------------------------------
__global__ void self_dot_kernel(const float* __restrict__ q,
                                const float* __restrict__ kt,
                                float* __restrict__ SC)
{
    int row  = blockIdx.x * 8 + (threadIdx.x >> 5);
    int lane = threadIdx.x & 31;
    const float4* q4 = (const float4*)(q  + (size_t)row * Hh);
    const float4* k4 = (const float4*)(kt + (size_t)row * Hh);
    float sum = 0.f;
    #pragma unroll
    for (int i = lane; i < Hh / 4; i += 32) {
        float4 a = q4[i], b = k4[i];
        sum += a.x * b.x + a.y * b.y + a.z * b.z + a.w * b.w;
    }
    #pragma unroll
    for (int o = 16; o; o >>= 1) sum += __shfl_xor_sync(0xffffffffu, sum, o);
    if (lane == 0) SC[(size_t)row * LS] = sum;
}

// ---------------------------------------------------------------------------
// Softmax over rows of length LS=513, in place. One block (128 thr) per row.
// ---------------------------------------------------------------------------
__global__ void softmax_kernel(float* __restrict__ SC)
{
    float* s = SC + (size_t)blockIdx.x * LS;
    const int tid = threadIdx.x;
    __shared__ float redm[4];
    __shared__ float reds[4];

    float v[5];
    float lmax = -INFINITY;
    #pragma unroll
    for (int i = 0; i < 5; i++) {
        int idx = tid + 128 * i;
        v[i] = (idx < LS) ? s[idx] : -INFINITY;
        lmax = fmaxf(lmax, v[i]);
    }
    #pragma unroll
    for (int o = 16; o; o >>= 1)
        lmax = fmaxf(lmax, __shfl_xor_sync(0xffffffffu, lmax, o));
    if ((tid & 31) == 0) redm[tid >> 5] = lmax;
    __syncthreads();
    float m = fmaxf(fmaxf(redm[0], redm[1]), fmaxf(redm[2], redm[3]));

    float lsum = 0.f;
    #pragma unroll
    for (int i = 0; i < 5; i++) {
        v[i] = expf(v[i] - m);
        lsum += v[i];
    }
    #pragma unroll
    for (int o = 16; o; o >>= 1) lsum += __shfl_xor_sync(0xffffffffu, lsum, o);
    if ((tid & 31) == 0) reds[tid >> 5] = lsum;
    __syncthreads();
    float inv = 1.f / (reds[0] + reds[1] + reds[2] + reds[3]);

    #pragma unroll
    for (int i = 0; i < 5; i++) {
        int idx = tid + 128 * i;
        if (idx < LS) s[idx] = v[i] * inv;
    }
}

// ---------------------------------------------------------------------------
// Context: O[b,s,:] = p0 * v_tok[b,s,:] + P[b,s,1:] @ V_ext[b]  (K = Ee)
// Tile 256(M) x 128(N), 512 threads.
// ---------------------------------------------------------------------------
__global__ void __launch_bounds__(512, 1) gemm_ctx(
    const float* __restrict__ P, const float* __restrict__ VE,
    const float* __restrict__ VT, float* __restrict__ O)
{
    SMEM_PTRS;
    const int b = blockIdx.z;
    const float* Bbase = VE + (size_t)b * Ee * Hh;

    const int bm = blockIdx.y * 256;
    const int bn = blockIdx.x * 128;
    WARP_IDS;
    const int ar = tid >> 2, ac = (tid & 3) << 2;
    const int br = tid >> 5, bc = (tid & 31) << 2;

    ACC_INIT;
    float pav[2][4];
    float4 pb0;

#define LOAD_C(k0)                                                            \
    do {                                                                      \
        const float* ap0 = P + (size_t)(b * Ss + bm + ar) * LS + 1 + (k0) + ac;       \
        const float* ap1 = P + (size_t)(b * Ss + bm + ar + 128) * LS + 1 + (k0) + ac; \
        pav[0][0] = ap0[0]; pav[0][1] = ap0[1];                               \
        pav[0][2] = ap0[2]; pav[0][3] = ap0[3];                               \
        pav[1][0] = ap1[0]; pav[1][1] = ap1[1];                               \
        pav[1][2] = ap1[2]; pav[1][3] = ap1[3];                               \
        pb0 = *(const float4*)(Bbase + (size_t)((k0) + br) * Hh + bn + bc);   \
    } while (0)
#define STS_C(As_, Bs_)                                                       \
    do {                                                                      \
        (As_)[(ac + 0) * RSA + ar] = pav[0][0];                               \
        (As_)[(ac + 1) * RSA + ar] = pav[0][1];                               \
        (As_)[(ac + 2) * RSA + ar] = pav[0][2];                               \
        (As_)[(ac + 3) * RSA + ar] = pav[0][3];                               \
        (As_)[(ac + 0) * RSA + ar + 128] = pav[1][0];                         \
        (As_)[(ac + 1) * RSA + ar + 128] = pav[1][1];                         \
        (As_)[(ac + 2) * RSA + ar + 128] = pav[1][2];                         \
        (As_)[(ac + 3) * RSA + ar + 128] = pav[1][3];                         \
        *(float4*)&(Bs_)[br * RSB + bc] = pb0;                                \
    } while (0)

    LOAD_C(0);
    STS_C(AsBase, BsBase);
    __syncthreads();
    int buf = 0;
    for (int k0 = 0; k0 < Ee; k0 += 16) {
        const bool nxt = (k0 + 16 < Ee);
        if (nxt) LOAD_C(k0 + 16);
        FRAG_COMPUTE((AsBase + buf * AT_FLOATS), (BsBase + buf * BT_FLOATS));
        if (nxt) STS_C((AsBase + (buf ^ 1) * AT_FLOATS),
                       (BsBase + (buf ^ 1) * BT_FLOATS));
        __syncthreads();
        buf ^= 1;
    }
#undef LOAD_C
#undef STS_C

    #pragma unroll
    for (int mt = 0; mt < 4; mt++) {
        int r0 = b * Ss + bm + wm * 64 + mt * 16 + gid;
        int r1 = r0 + 8;
        float p0 = P[(size_t)r0 * LS];
        float p1 = P[(size_t)r1 * LS];
        #pragma unroll
        for (int nt = 0; nt < 4; nt++) {
            int col = bn + wn * 32 + nt * 8 + 2 * tg;
            float2 v0 = *(const float2*)(VT + (size_t)r0 * Hh + col);
            float2 v1 = *(const float2*)(VT + (size_t)r1 * Hh + col);
            float2 o0 = make_float2(fmaf(p0, v0.x, acc[mt][nt][0]),
                                    fmaf(p0, v0.y, acc[mt][nt][1]));
            float2 o1 = make_float2(fmaf(p1, v1.x, acc[mt][nt][2]),
                                    fmaf(p1, v1.y, acc[mt][nt][3]));
            *(float2*)(O + (size_t)r0 * Hh + col) = o0;
            *(float2*)(O + (size_t)r1 * Hh + col) = o1;
        }
    }
}

// ---------------------------------------------------------------------------
extern "C" void kernel_launch(void* const* d_in, const int* in_sizes, int n_in,
                              void* d_out, int out_size)
{
    const float* hs  = (const float*)d_in[0];
    const float* ext = (const float*)d_in[1];
    const float* Wq  = (const float*)d_in[2];
    const float* bq  = (const float*)d_in[3];
    const float* Wk  = (const float*)d_in[4];
    const float* bk  = (const float*)d_in[5];
    const float* Wv  = (const float*)d_in[6];
    const float* bv  = (const float*)d_in[7];
    float* out = (float*)d_out;

    float *q, *kt, *vt, *ke, *ve, *sc;
    cudaGetSymbolAddress((void**)&q,  g_q);
    cudaGetSymbolAddress((void**)&kt, g_kt);
    cudaGetSymbolAddress((void**)&vt, g_vt);
    cudaGetSymbolAddress((void**)&ke, g_ke);
    cudaGetSymbolAddress((void**)&ve, g_ve);
    cudaGetSymbolAddress((void**)&sc, g_sc);

    cudaFuncSetAttribute(gemm_proj,
        cudaFuncAttributeMaxDynamicSharedMemorySize, SMEM_BYTES);
    cudaFuncSetAttribute(gemm_scores_nt,
        cudaFuncAttributeMaxDynamicSharedMemorySize, SMEM_BYTES);
    cudaFuncSetAttribute(gemm_ctx,
        cudaFuncAttributeMaxDynamicSharedMemorySize, SMEM_BYTES);

    dim3 blk(512);

    // Token projections (q, k_tok, v_tok) in one z-indexed launch
    gemm_proj<<<dim3(Hh / 128, BS / 256, 3), blk, SMEM_BYTES>>>(
        hs, Wq, Wk, Wv, bq, bk, bv, q, kt, vt);
    // External projections (k_ext, v_ext)
    gemm_proj<<<dim3(Hh / 128, BE / 256, 2), blk, SMEM_BYTES>>>(
        ext, Wk, Wv, Wv, bk, bv, bv, ke, ve, ve);

    // Scores
    self_dot_kernel<<<BS / 8, 256>>>(q, kt, sc);
    gemm_scores_nt<<<dim3(Ee / 128, Ss / 256, Bb), blk, SMEM_BYTES>>>(q, ke, sc);

    // Softmax
    softmax_kernel<<<BS, 128>>>(sc);

    // Context
    gemm_ctx<<<dim3(Hh / 128, Ss / 256, Bb), blk, SMEM_BYTES>>>(sc, ve, vt, out);
}

// round 7
// speedup vs baseline: 1.9450x; 1.3409x over previous
#include <cuda_runtime.h>
#include <cuda_fp16.h>
#include <cstdint>
#include <math.h>

// Problem dims (fixed)
#define Bb 4
#define Ss 2048
#define Ee 512
#define Hh 1024
#define BS (Bb*Ss)
#define BE (Bb*Ee)

// Scratch (device globals; allocation-free)
__device__ float g_q [BS*Hh];
__device__ float g_kt[BS*Hh];
__device__ float g_vt[BS*Hh];
__device__ float g_ke[BE*Hh];
__device__ float g_ve[BE*Hh];
__device__ float g_sc[(size_t)BS*512];   // ext scores/probs (stride 512, aligned)
__device__ float g_s0[BS];               // self score / prob

// Interleaved (hi,lo) fp16x2 tiles: rows = 8 k-pairs, 128 m/n columns (uint2).
#define RP 132                           // uint2 row stride; 2*132 % 32 == 8
#define TILE_U2 (8 * RP)

// Split two fp32 (consecutive k) into packed fp16x2 hi + lo. low half = x.
__device__ __forceinline__ void split2(float x, float y,
                                       uint32_t &h, uint32_t &l)
{
    asm("cvt.rn.f16x2.f32 %0, %1, %2;" : "=r"(h) : "f"(y), "f"(x));
    __half2 hv = *reinterpret_cast<__half2*>(&h);
    float2 b = __half22float2(hv);
    asm("cvt.rn.f16x2.f32 %0, %1, %2;" : "=r"(l) : "f"(y - b.y), "f"(x - b.x));
}

__device__ __forceinline__ void mma16(float* d, const uint32_t* a,
                                      const uint32_t* b)
{
    asm volatile(
        "mma.sync.aligned.m16n8k16.row.col.f32.f16.f16.f32 "
        "{%0,%1,%2,%3}, {%4,%5,%6,%7}, {%8,%9}, {%0,%1,%2,%3};"
        : "+f"(d[0]), "+f"(d[1]), "+f"(d[2]), "+f"(d[3])
        : "r"(a[0]), "r"(a[1]), "r"(a[2]), "r"(a[3]),
          "r"(b[0]), "r"(b[1]));
}

// One K=16 step, 3-term emulation (hh, hl, lh).
#define FRAG_COMPUTE(Abuf, Bbuf)                                              \
  do {                                                                        \
    uint32_t ah[4][4], al[4][4], bh[4][2], bl[4][2];                          \
    _Pragma("unroll")                                                         \
    for (int mt = 0; mt < 4; mt++) {                                          \
      int mb = wm * 64 + mt * 16 + gid;                                       \
      uint2 v00 = (Abuf)[tg * RP + mb];                                       \
      uint2 v01 = (Abuf)[tg * RP + mb + 8];                                   \
      uint2 v10 = (Abuf)[(tg + 4) * RP + mb];                                 \
      uint2 v11 = (Abuf)[(tg + 4) * RP + mb + 8];                             \
      ah[mt][0] = v00.x; ah[mt][1] = v01.x;                                   \
      ah[mt][2] = v10.x; ah[mt][3] = v11.x;                                   \
      al[mt][0] = v00.y; al[mt][1] = v01.y;                                   \
      al[mt][2] = v10.y; al[mt][3] = v11.y;                                   \
    }                                                                         \
    _Pragma("unroll")                                                         \
    for (int nt = 0; nt < 4; nt++) {                                          \
      int nb = wn * 32 + nt * 8 + gid;                                        \
      uint2 w0 = (Bbuf)[tg * RP + nb];                                        \
      uint2 w1 = (Bbuf)[(tg + 4) * RP + nb];                                  \
      bh[nt][0] = w0.x; bh[nt][1] = w1.x;                                     \
      bl[nt][0] = w0.y; bl[nt][1] = w1.y;                                     \
    }                                                                         \
    _Pragma("unroll")                                                         \
    for (int mt = 0; mt < 4; mt++)                                            \
      _Pragma("unroll")                                                       \
      for (int nt = 0; nt < 4; nt++) {                                        \
        mma16(acc[mt][nt], ah[mt], bh[nt]);                                   \
        mma16(acc[mt][nt], ah[mt], bl[nt]);                                   \
        mma16(acc[mt][nt], al[mt], bh[nt]);                                   \
      }                                                                       \
  } while (0)

#define ACC_INIT                                                              \
    float acc[4][4][4];                                                      \
    _Pragma("unroll")                                                         \
    for (int i = 0; i < 4; i++)                                               \
      _Pragma("unroll")                                                       \
      for (int j = 0; j < 4; j++)                                             \
        _Pragma("unroll")                                                     \
        for (int t = 0; t < 4; t++) acc[i][j][t] = 0.f;

#define WARP_IDS                                                              \
    const int tid = threadIdx.x;                                              \
    const int warp = tid >> 5, lane = tid & 31;                               \
    const int wm = warp & 1, wn = warp >> 1;                                  \
    const int gid = lane >> 2, tg = lane & 3;

#define SMEM_DECL                                                             \
    __shared__ uint2 As[2][TILE_U2];                                          \
    __shared__ uint2 Bs[2][TILE_U2];

// A-side STS: transpose a float4 (4 consecutive k of one row) into k-pair tiles
#define STS_A4(As_, kp0, m, v)                                                \
    do {                                                                      \
        uint32_t h_, l_;                                                      \
        split2((v).x, (v).y, h_, l_);                                         \
        (As_)[(kp0) * RP + (m)] = make_uint2(h_, l_);                         \
        split2((v).z, (v).w, h_, l_);                                         \
        (As_)[((kp0) + 1) * RP + (m)] = make_uint2(h_, l_);                   \
    } while (0)

// B-side STS: two k-rows (even/odd), 4 n values, optional scale
#define STS_B8(Bs_, br_, bc_, p0, p1, s)                                      \
    do {                                                                      \
        uint32_t h0,l0,h1,l1,h2,l2,h3,l3;                                     \
        split2((s)*(p0).x, (s)*(p1).x, h0, l0);                               \
        split2((s)*(p0).y, (s)*(p1).y, h1, l1);                               \
        split2((s)*(p0).z, (s)*(p1).z, h2, l2);                               \
        split2((s)*(p0).w, (s)*(p1).w, h3, l3);                               \
        *(uint4*)&(Bs_)[(br_) * RP + (bc_)]     = make_uint4(h0,l0,h1,l1);    \
        *(uint4*)&(Bs_)[(br_) * RP + (bc_) + 2] = make_uint4(h2,l2,h3,l3);    \
    } while (0)

#define WSCALE 32.0f
#define WINV   (1.0f / 32.0f)

// ---------------------------------------------------------------------------
// Projection: C = A[M,1024] @ W[1024,1024] + bias. 128x128 tile, BK=16.
// W pre-scaled by 32 at convert (keeps lo parts fp16-normal); epilogue /32.
// ---------------------------------------------------------------------------
__global__ void __launch_bounds__(256) gemm_proj(
    const float* __restrict__ A, const float* __restrict__ W,
    const float* __restrict__ bias, float* __restrict__ C, int M)
{
    SMEM_DECL;
    const int bm = blockIdx.y * 128;
    const int bn = blockIdx.x * 128;
    WARP_IDS;
    const int ar = tid >> 2, ac = (tid & 3) << 2;
    const int br = tid >> 5, bc = (tid & 31) << 2;

    ACC_INIT;
    float4 pa0, pa1, pb0, pb1;

#define LOAD_P(k0)                                                            \
    do {                                                                      \
        pa0 = *(const float4*)(A + (size_t)(bm + ar) * Hh + (k0) + ac);       \
        pa1 = *(const float4*)(A + (size_t)(bm + ar + 64) * Hh + (k0) + ac);  \
        pb0 = *(const float4*)(W + (size_t)((k0) + 2*br) * Hh + bn + bc);     \
        pb1 = *(const float4*)(W + (size_t)((k0) + 2*br + 1) * Hh + bn + bc); \
    } while (0)
#define STS_P(s)                                                              \
    do {                                                                      \
        STS_A4(As[s], ac >> 1, ar, pa0);                                      \
        STS_A4(As[s], ac >> 1, ar + 64, pa1);                                 \
        STS_B8(Bs[s], br, bc, pb0, pb1, WSCALE);                              \
    } while (0)

    LOAD_P(0);
    STS_P(0);
    __syncthreads();
    int buf = 0;
    for (int k0 = 0; k0 < Hh; k0 += 16) {
        const bool nxt = (k0 + 16 < Hh);
        if (nxt) LOAD_P(k0 + 16);
        FRAG_COMPUTE(As[buf], Bs[buf]);
        if (nxt) STS_P(buf ^ 1);
        __syncthreads();
        buf ^= 1;
    }
#undef LOAD_P
#undef STS_P

    #pragma unroll
    for (int mt = 0; mt < 4; mt++) {
        int r0 = bm + wm * 64 + mt * 16 + gid;
        #pragma unroll
        for (int nt = 0; nt < 4; nt++) {
            int col = bn + wn * 32 + nt * 8 + 2 * tg;
            float2 bi = *(const float2*)(bias + col);
            float2 o0 = make_float2(fmaf(acc[mt][nt][0], WINV, bi.x),
                                    fmaf(acc[mt][nt][1], WINV, bi.y));
            float2 o1 = make_float2(fmaf(acc[mt][nt][2], WINV, bi.x),
                                    fmaf(acc[mt][nt][3], WINV, bi.y));
            *(float2*)(C + (size_t)r0 * Hh + col) = o0;
            *(float2*)(C + (size_t)(r0 + 8) * Hh + col) = o1;
        }
    }
}

// ---------------------------------------------------------------------------
// Scores: SC[b, s, e] = Q[b,s,:] . KE[b,e,:]  (K = 1024), stride-512 output
// ---------------------------------------------------------------------------
__global__ void __launch_bounds__(256) gemm_scores_nt(
    const float* __restrict__ Q, const float* __restrict__ KE,
    float* __restrict__ SC)
{
    SMEM_DECL;
    const int b = blockIdx.z;
    const float* Aq = Q  + (size_t)b * Ss * Hh;
    const float* Bk = KE + (size_t)b * Ee * Hh;
    const int bm = blockIdx.y * 128;
    const int bn = blockIdx.x * 128;
    WARP_IDS;
    const int ar = tid >> 2, ac = (tid & 3) << 2;

    ACC_INIT;
    float4 pa0, pa1, pb0, pb1;

#define LOAD_S(k0)                                                            \
    do {                                                                      \
        pa0 = *(const float4*)(Aq + (size_t)(bm + ar) * Hh + (k0) + ac);      \
        pa1 = *(const float4*)(Aq + (size_t)(bm + ar + 64) * Hh + (k0) + ac); \
        pb0 = *(const float4*)(Bk + (size_t)(bn + ar) * Hh + (k0) + ac);      \
        pb1 = *(const float4*)(Bk + (size_t)(bn + ar + 64) * Hh + (k0) + ac); \
    } while (0)
#define STS_S(s)                                                              \
    do {                                                                      \
        STS_A4(As[s], ac >> 1, ar, pa0);                                      \
        STS_A4(As[s], ac >> 1, ar + 64, pa1);                                 \
        STS_A4(Bs[s], ac >> 1, ar, pb0);                                      \
        STS_A4(Bs[s], ac >> 1, ar + 64, pb1);                                 \
    } while (0)

    LOAD_S(0);
    STS_S(0);
    __syncthreads();
    int buf = 0;
    for (int k0 = 0; k0 < Hh; k0 += 16) {
        const bool nxt = (k0 + 16 < Hh);
        if (nxt) LOAD_S(k0 + 16);
        FRAG_COMPUTE(As[buf], Bs[buf]);
        if (nxt) STS_S(buf ^ 1);
        __syncthreads();
        buf ^= 1;
    }
#undef LOAD_S
#undef STS_S

    #pragma unroll
    for (int mt = 0; mt < 4; mt++) {
        int row = b * Ss + bm + wm * 64 + mt * 16 + gid;
        #pragma unroll
        for (int nt = 0; nt < 4; nt++) {
            int col = bn + wn * 32 + nt * 8 + 2 * tg;
            *(float2*)(SC + (size_t)row * 512 + col) =
                make_float2(acc[mt][nt][0], acc[mt][nt][1]);
            *(float2*)(SC + (size_t)(row + 8) * 512 + col) =
                make_float2(acc[mt][nt][2], acc[mt][nt][3]);
        }
    }
}

// ---------------------------------------------------------------------------
// Context: O = P[.,512] @ VE[512,1024] + p0 * VT   (K = 512)
// ---------------------------------------------------------------------------
__global__ void __launch_bounds__(256) gemm_ctx(
    const float* __restrict__ P, const float* __restrict__ P0,
    const float* __restrict__ VE, const float* __restrict__ VT,
    float* __restrict__ O)
{
    SMEM_DECL;
    const int b = blockIdx.z;
    const float* Bbase = VE + (size_t)b * Ee * Hh;
    const int bm = blockIdx.y * 128;
    const int bn = blockIdx.x * 128;
    WARP_IDS;
    const int ar = tid >> 2, ac = (tid & 3) << 2;
    const int br = tid >> 5, bc = (tid & 31) << 2;

    ACC_INIT;
    float4 pa0, pa1, pb0, pb1;

#define LOAD_C(k0)                                                            \
    do {                                                                      \
        pa0 = *(const float4*)(P + (size_t)(b * Ss + bm + ar) * 512 + (k0) + ac);      \
        pa1 = *(const float4*)(P + (size_t)(b * Ss + bm + ar + 64) * 512 + (k0) + ac); \
        pb0 = *(const float4*)(Bbase + (size_t)((k0) + 2*br) * Hh + bn + bc);          \
        pb1 = *(const float4*)(Bbase + (size_t)((k0) + 2*br + 1) * Hh + bn + bc);      \
    } while (0)
#define STS_C(s)                                                              \
    do {                                                                      \
        STS_A4(As[s], ac >> 1, ar, pa0);                                      \
        STS_A4(As[s], ac >> 1, ar + 64, pa1);                                 \
        STS_B8(Bs[s], br, bc, pb0, pb1, 1.0f);                                \
    } while (0)

    LOAD_C(0);
    STS_C(0);
    __syncthreads();
    int buf = 0;
    for (int k0 = 0; k0 < Ee; k0 += 16) {
        const bool nxt = (k0 + 16 < Ee);
        if (nxt) LOAD_C(k0 + 16);
        FRAG_COMPUTE(As[buf], Bs[buf]);
        if (nxt) STS_C(buf ^ 1);
        __syncthreads();
        buf ^= 1;
    }
#undef LOAD_C
#undef STS_C

    #pragma unroll
    for (int mt = 0; mt < 4; mt++) {
        int r0 = b * Ss + bm + wm * 64 + mt * 16 + gid;
        int r1 = r0 + 8;
        float p0 = P0[r0];
        float p1 = P0[r1];
        #pragma unroll
        for (int nt = 0; nt < 4; nt++) {
            int col = bn + wn * 32 + nt * 8 + 2 * tg;
            float2 v0 = *(const float2*)(VT + (size_t)r0 * Hh + col);
            float2 v1 = *(const float2*)(VT + (size_t)r1 * Hh + col);
            float2 o0 = make_float2(fmaf(p0, v0.x, acc[mt][nt][0]),
                                    fmaf(p0, v0.y, acc[mt][nt][1]));
            float2 o1 = make_float2(fmaf(p1, v1.x, acc[mt][nt][2]),
                                    fmaf(p1, v1.y, acc[mt][nt][3]));
            *(float2*)(O + (size_t)r0 * Hh + col) = o0;
            *(float2*)(O + (size_t)r1 * Hh + col) = o1;
        }
    }
}

// ---------------------------------------------------------------------------
// Self-dot: S0[row] = q[row,:] . k_tok[row,:]   (fp32, one warp per row)
// ---------------------------------------------------------------------------
__global__ void self_dot_kernel(const float* __restrict__ q,
                                const float* __restrict__ kt,
                                float* __restrict__ S0)
{
    int row  = blockIdx.x * 8 + (threadIdx.x >> 5);
    int lane = threadIdx.x & 31;
    const float4* q4 = (const float4*)(q  + (size_t)row * Hh);
    const float4* k4 = (const float4*)(kt + (size_t)row * Hh);
    float sum = 0.f;
    #pragma unroll
    for (int i = lane; i < Hh / 4; i += 32) {
        float4 a = q4[i], b = k4[i];
        sum += a.x * b.x + a.y * b.y + a.z * b.z + a.w * b.w;
    }
    #pragma unroll
    for (int o = 16; o; o >>= 1) sum += __shfl_xor_sync(0xffffffffu, sum, o);
    if (lane == 0) S0[row] = sum;
}

// ---------------------------------------------------------------------------
// Softmax over {S0[row]} ++ SC[row][0..511], in place. 128 threads/row.
// ---------------------------------------------------------------------------
__global__ void softmax_kernel(float* __restrict__ SC, float* __restrict__ S0)
{
    const int row = blockIdx.x;
    float* s = SC + (size_t)row * 512;
    const int tid = threadIdx.x;
    __shared__ float redm[4], reds[4];

    float4 v = ((float4*)s)[tid];
    float s0 = S0[row];
    float lmax = fmaxf(fmaxf(v.x, v.y), fmaxf(v.z, v.w));
    if (tid == 0) lmax = fmaxf(lmax, s0);
    #pragma unroll
    for (int o = 16; o; o >>= 1)
        lmax = fmaxf(lmax, __shfl_xor_sync(0xffffffffu, lmax, o));
    if ((tid & 31) == 0) redm[tid >> 5] = lmax;
    __syncthreads();
    float m = fmaxf(fmaxf(redm[0], redm[1]), fmaxf(redm[2], redm[3]));

    v.x = expf(v.x - m); v.y = expf(v.y - m);
    v.z = expf(v.z - m); v.w = expf(v.w - m);
    float e0 = expf(s0 - m);
    float lsum = v.x + v.y + v.z + v.w + ((tid == 0) ? e0 : 0.f);
    #pragma unroll
    for (int o = 16; o; o >>= 1) lsum += __shfl_xor_sync(0xffffffffu, lsum, o);
    if ((tid & 31) == 0) reds[tid >> 5] = lsum;
    __syncthreads();
    float inv = 1.f / (reds[0] + reds[1] + reds[2] + reds[3]);

    v.x *= inv; v.y *= inv; v.z *= inv; v.w *= inv;
    ((float4*)s)[tid] = v;
    if (tid == 0) S0[row] = e0 * inv;
}

// ---------------------------------------------------------------------------
extern "C" void kernel_launch(void* const* d_in, const int* in_sizes, int n_in,
                              void* d_out, int out_size)
{
    const float* hs  = (const float*)d_in[0];
    const float* ext = (const float*)d_in[1];
    const float* Wq  = (const float*)d_in[2];
    const float* bq  = (const float*)d_in[3];
    const float* Wk  = (const float*)d_in[4];
    const float* bk  = (const float*)d_in[5];
    const float* Wv  = (const float*)d_in[6];
    const float* bv  = (const float*)d_in[7];
    float* out = (float*)d_out;

    float *q, *kt, *vt, *ke, *ve, *sc, *s0;
    cudaGetSymbolAddress((void**)&q,  g_q);
    cudaGetSymbolAddress((void**)&kt, g_kt);
    cudaGetSymbolAddress((void**)&vt, g_vt);
    cudaGetSymbolAddress((void**)&ke, g_ke);
    cudaGetSymbolAddress((void**)&ve, g_ve);
    cudaGetSymbolAddress((void**)&sc, g_sc);
    cudaGetSymbolAddress((void**)&s0, g_s0);

    dim3 blk(256);

    // Projections (fp16 3-term split, weights x32)
    gemm_proj<<<dim3(8, BS / 128), blk>>>(hs,  Wq, bq, q,  BS);
    gemm_proj<<<dim3(8, BS / 128), blk>>>(hs,  Wk, bk, kt, BS);
    gemm_proj<<<dim3(8, BS / 128), blk>>>(hs,  Wv, bv, vt, BS);
    gemm_proj<<<dim3(8, BE / 128), blk>>>(ext, Wk, bk, ke, BE);
    gemm_proj<<<dim3(8, BE / 128), blk>>>(ext, Wv, bv, ve, BE);

    // Scores
    self_dot_kernel<<<BS / 8, 256>>>(q, kt, s0);
    gemm_scores_nt<<<dim3(4, Ss / 128, Bb), blk>>>(q, ke, sc);

    // Softmax (self + 512 ext)
    softmax_kernel<<<BS, 128>>>(sc, s0);

    // Context
    gemm_ctx<<<dim3(8, Ss / 128, Bb), blk>>>(sc, s0, ve, vt, out);
}